// round 14
// baseline (speedup 1.0000x reference)
#include <cuda_runtime.h>

// AttentionFusion: fused = sigmoid((x1-x2)@w) * x1 + (1-sigmoid) * x2
// N = 16384 rows, D = 2048 cols, fp32. Pure HBM streamer (~402 MB min traffic).
//
// R13: geometry test driven by the B300 cross-CTA L1tex spread model
//   spr_max = 1.10 + 25*(oe*MLP_p1 - 16)/T_CTA
// R12 (256 thr, MLP_p1=6, oe=8): oe*MLP=48 >> 16 -> straggler spread.
// R13: 512 thr/CTA, 1 float4 per stream per thread -> MLP_p1=3, oe=4,
// oe*MLP=12 < 16 -> spread at floor. Same 64 warps/SM, same one-shot CTA
// churn, same single barrier, no cache hints (R12 lesson).

#define N_ROWS 16384
#define D_COLS 2048
#define THREADS 512
#define NWARPS (THREADS / 32)   // 16

__global__ __launch_bounds__(THREADS, 4)
void attention_fusion_kernel(const float* __restrict__ x1,
                             const float* __restrict__ x2,
                             const float* __restrict__ w,
                             float* __restrict__ fused,
                             float2* __restrict__ alpha) {
    const int row  = blockIdx.x;
    const int tid  = threadIdx.x;
    const int lane = tid & 31;
    const int warp = tid >> 5;

    const float4* __restrict__ x1r = reinterpret_cast<const float4*>(x1) + (size_t)row * (D_COLS / 4);
    const float4* __restrict__ x2r = reinterpret_cast<const float4*>(x2) + (size_t)row * (D_COLS / 4);
    const float4* __restrict__ w4  = reinterpret_cast<const float4*>(w);

    // One LDG.128 per stream per thread (MLP_p1 = 3), default caching
    float4 a0 = x1r[tid];
    float4 b0 = x2r[tid];
    float4 w0 = w4[tid];

    // Partial of d = dot(x1 - x2, w)
    float d = (a0.x - b0.x) * w0.x;
    d = fmaf(a0.y - b0.y, w0.y, d);
    d = fmaf(a0.z - b0.z, w0.z, d);
    d = fmaf(a0.w - b0.w, w0.w, d);

    // Warp reduce
    #pragma unroll
    for (int off = 16; off > 0; off >>= 1)
        d += __shfl_xor_sync(0xFFFFFFFFu, d, off);

    __shared__ float warp_sums[NWARPS];
    if (lane == 0) warp_sums[warp] = d;
    __syncthreads();   // the only barrier

    // Every thread finishes the 16-way reduction itself (broadcast LDS)
    float v = warp_sums[0];
    #pragma unroll
    for (int i = 1; i < NWARPS; i++) v += warp_sums[i];

    // Fast sigmoid: 2 MUFU ops; tolerance 1e-3, this is ~1e-7
    const float al = __frcp_rn(1.0f + __expf(-v));

    if (tid == 0) {
        alpha[row] = make_float2(al, 1.0f - al);
    }

    float4* __restrict__ outr = reinterpret_cast<float4*>(fused) + (size_t)row * (D_COLS / 4);

    float4 o0;
    o0.x = fmaf(al, a0.x - b0.x, b0.x);   // al*a + (1-al)*b = al*(a-b) + b
    o0.y = fmaf(al, a0.y - b0.y, b0.y);
    o0.z = fmaf(al, a0.z - b0.z, b0.z);
    o0.w = fmaf(al, a0.w - b0.w, b0.w);

    outr[tid] = o0;
}

extern "C" void kernel_launch(void* const* d_in, const int* in_sizes, int n_in,
                              void* d_out, int out_size) {
    const float* x1 = (const float*)d_in[0];
    const float* x2 = (const float*)d_in[1];
    const float* w  = (const float*)d_in[2];
    float* out = (float*)d_out;

    float*  fused = out;                                                      // [N, D]
    float2* alpha = reinterpret_cast<float2*>(out + (size_t)N_ROWS * D_COLS); // [N, 2]

    attention_fusion_kernel<<<N_ROWS, THREADS>>>(x1, x2, w, fused, alpha);
}

// round 15
// speedup vs baseline: 1.0480x; 1.0480x over previous
#include <cuda_runtime.h>

// AttentionFusion: fused = sigmoid((x1-x2)@w) * x1 + (1-sigmoid) * x2
// N = 16384 rows, D = 2048 cols, fp32. Pure HBM streamer.
//
// FINAL (R12 form). Converged design after measuring the full neighborhood:
//  - one-shot CTA per row: CTA churn IS the software pipeline (persistent
//    CTAs serialize the load queue at barriers: 73% DRAM)
//  - 256 thr, 2 float4/thread/stream -> 6 front-batched LDG.128 per thread,
//    32 regs, occ 8 CTAs/SM (64 warps). 512thr/MLP3 loses (76%), occ-4
//    pipelined loses (79%)
//  - default caching: __ldcs/__stcs cost ~2us (evict-first shrinks L2's
//    DRAM-burst aggregation window)
//  - single barrier; every thread redundantly finishes the 8-way reduce
//  - fast sigmoid (__expf + __frcp_rn), float2 alpha store
// Measured: ~53us kernel, 84% DRAM active, 6.7 TB/s — machine ceiling for
// this read/write mix; residual idle is bus turnaround + wave tail.

#define N_ROWS 16384
#define D_COLS 2048
#define THREADS 256
#define NWARPS (THREADS / 32)

__global__ __launch_bounds__(THREADS, 8)
void attention_fusion_kernel(const float* __restrict__ x1,
                             const float* __restrict__ x2,
                             const float* __restrict__ w,
                             float* __restrict__ fused,
                             float2* __restrict__ alpha) {
    const int row  = blockIdx.x;
    const int tid  = threadIdx.x;
    const int lane = tid & 31;
    const int warp = tid >> 5;

    const float4* __restrict__ x1r = reinterpret_cast<const float4*>(x1) + (size_t)row * (D_COLS / 4);
    const float4* __restrict__ x2r = reinterpret_cast<const float4*>(x2) + (size_t)row * (D_COLS / 4);
    const float4* __restrict__ w4  = reinterpret_cast<const float4*>(w);

    // Front-batched coalesced LDG.128s (6 per thread), default caching
    float4 a0 = x1r[tid];
    float4 a1 = x1r[tid + THREADS];
    float4 b0 = x2r[tid];
    float4 b1 = x2r[tid + THREADS];
    float4 w0 = w4[tid];
    float4 w1 = w4[tid + THREADS];

    // Partial of d = dot(x1 - x2, w)
    float d = (a0.x - b0.x) * w0.x;
    d = fmaf(a0.y - b0.y, w0.y, d);
    d = fmaf(a0.z - b0.z, w0.z, d);
    d = fmaf(a0.w - b0.w, w0.w, d);
    d = fmaf(a1.x - b1.x, w1.x, d);
    d = fmaf(a1.y - b1.y, w1.y, d);
    d = fmaf(a1.z - b1.z, w1.z, d);
    d = fmaf(a1.w - b1.w, w1.w, d);

    // Warp reduce
    #pragma unroll
    for (int off = 16; off > 0; off >>= 1)
        d += __shfl_xor_sync(0xFFFFFFFFu, d, off);

    __shared__ float warp_sums[NWARPS];
    if (lane == 0) warp_sums[warp] = d;
    __syncthreads();   // the only barrier

    // Every thread finishes the reduction itself (conflict-free broadcast LDS)
    float v = warp_sums[0];
    #pragma unroll
    for (int i = 1; i < NWARPS; i++) v += warp_sums[i];

    // Fast sigmoid: 2 MUFU ops; tolerance 1e-3, error here ~1e-7
    const float al = __frcp_rn(1.0f + __expf(-v));

    if (tid == 0) {
        alpha[row] = make_float2(al, 1.0f - al);
    }

    float4* __restrict__ outr = reinterpret_cast<float4*>(fused) + (size_t)row * (D_COLS / 4);

    float4 o0, o1;
    o0.x = fmaf(al, a0.x - b0.x, b0.x);   // al*a + (1-al)*b = al*(a-b) + b
    o0.y = fmaf(al, a0.y - b0.y, b0.y);
    o0.z = fmaf(al, a0.z - b0.z, b0.z);
    o0.w = fmaf(al, a0.w - b0.w, b0.w);
    o1.x = fmaf(al, a1.x - b1.x, b1.x);
    o1.y = fmaf(al, a1.y - b1.y, b1.y);
    o1.z = fmaf(al, a1.z - b1.z, b1.z);
    o1.w = fmaf(al, a1.w - b1.w, b1.w);

    outr[tid] = o0;
    outr[tid + THREADS] = o1;
}

extern "C" void kernel_launch(void* const* d_in, const int* in_sizes, int n_in,
                              void* d_out, int out_size) {
    const float* x1 = (const float*)d_in[0];
    const float* x2 = (const float*)d_in[1];
    const float* w  = (const float*)d_in[2];
    float* out = (float*)d_out;

    float*  fused = out;                                                      // [N, D]
    float2* alpha = reinterpret_cast<float2*>(out + (size_t)N_ROWS * D_COLS); // [N, 2]

    attention_fusion_kernel<<<N_ROWS, THREADS>>>(x1, x2, w, fused, alpha);
}